// round 15
// baseline (speedup 1.0000x reference)
#include <cuda_runtime.h>
#include <cuda_bf16.h>
#include <math.h>
#include <stdint.h>

#define FULL 0xFFFFFFFFu

// ---------------- scratch (device globals; no allocation allowed) -------------
__device__ float    g_ada[2 * 256];                 // [B, 2C] scale|shift
__device__ uint32_t g_y_hi[2 * 64 * 64 * 64];       // LN out hi, bf16x2, k-perm
__device__ uint32_t g_y_lo[2 * 64 * 64 * 64];       // LN out lo
__device__ uint32_t g_wqT_hi[384 * 64];             // qkv_w^T hi [n][kpair]
__device__ uint32_t g_wqT_lo[384 * 64];
__device__ uint32_t g_wpT_hi[128 * 64];             // proj_w^T hi
__device__ uint32_t g_wpT_lo[128 * 64];
__device__ float    g_q[2 * 4 * 64 * 64 * 32];      // [B,n,H,W,d]
__device__ float    g_k[2 * 4 * 64 * 64 * 32];
__device__ float    g_v[2 * 4 * 64 * 64 * 32];
__device__ uint32_t g_att_hi[2 * 64 * 64 * 64];     // attention out hi, k-perm
__device__ uint32_t g_att_lo[2 * 64 * 64 * 64];

__device__ __forceinline__ int nb_start(int i) {
    int s = i - 3;
    s = s < 0 ? 0 : s;
    return s > 57 ? 57 : s;   // L-K = 64-7
}

// k-pair permutation: logical u32 index t -> physical position.
__device__ __forceinline__ int kperm(int t) {
    return (t & ~7) | ((t & 3) << 1) | ((t >> 2) & 1);
}

// split fp32 into bf16 hi and bf16 lo (as u16 bit patterns in u32)
__device__ __forceinline__ void bsplit(float x, uint32_t& h, uint32_t& l) {
    __nv_bfloat16 hb = __float2bfloat16(x);
    h = (uint32_t)__bfloat16_as_ushort(hb);
    l = (uint32_t)__bfloat16_as_ushort(__float2bfloat16(x - __bfloat162float(hb)));
}

__device__ __forceinline__ void mma_bf16(float* d, const uint32_t* a, const uint32_t* b) {
    asm("mma.sync.aligned.m16n8k16.row.col.f32.bf16.bf16.f32 "
        "{%0,%1,%2,%3}, {%4,%5,%6,%7}, {%8,%9}, {%0,%1,%2,%3};"
        : "+f"(d[0]), "+f"(d[1]), "+f"(d[2]), "+f"(d[3])
        : "r"(a[0]), "r"(a[1]), "r"(a[2]), "r"(a[3]), "r"(b[0]), "r"(b[1]));
}

// ---------------- kernel A: adaLN (blocks 0-1) + weight pack (blocks 2-9) -----
__global__ void adaln_pack(const int* __restrict__ t,
                           const float* __restrict__ ln_w,
                           const float* __restrict__ ln_b,
                           const float* __restrict__ qkv_w,
                           const float* __restrict__ proj_w) {
    __shared__ float tile[128][65];
    const int tid = threadIdx.x;

    if (blockIdx.x < 2) {
        float* s_silu = &tile[0][0];                 // reuse smem
        const int b = blockIdx.x;
        const float tf = (float)t[b] * 40.0f;        // t/100*4000
        if (tid < 64) {
            float f = __expf(-(float)tid * (9.210340371976184f / 63.0f));
            float e = tf * f;
            float se = sinf(e), ce = cosf(e);
            s_silu[tid]      = se / (1.0f + __expf(-se));
            s_silu[tid + 64] = ce / (1.0f + __expf(-ce));
        }
        __syncthreads();
        const int j = tid;
        float acc = ln_b[j];
#pragma unroll 16
        for (int k = 0; k < 128; k++) acc += s_silu[k] * ln_w[k * 256 + j];
        g_ada[b * 256 + j] = acc;
        return;
    }

    const int pb = blockIdx.x - 2;                   // 0..7
    const bool is_q = pb < 6;
    const float* W = is_q ? qkv_w : proj_w;
    const int stride = is_q ? 384 : 128;
    const int nbase = is_q ? pb * 64 : (pb - 6) * 64;
    uint32_t* dhi = is_q ? g_wqT_hi : g_wpT_hi;
    uint32_t* dlo = is_q ? g_wqT_lo : g_wpT_lo;

    for (int i = tid; i < 128 * 64; i += 256) {
        const int k = i >> 6, nn = i & 63;
        tile[k][nn] = W[k * stride + nbase + nn];
    }
    __syncthreads();

    for (int i = tid; i < 64 * 64; i += 256) {
        const int nn = i >> 6, tt = i & 63;
        uint32_t h0, l0, h1, l1;
        bsplit(tile[2 * tt][nn], h0, l0);
        bsplit(tile[2 * tt + 1][nn], h1, l1);
        const int pos = ((nbase + nn) << 6) | kperm(tt);
        dhi[pos] = h0 | (h1 << 16);
        dlo[pos] = l0 | (l1 << 16);
    }
}

// ---------------- kernel B: LayerNorm + modulate -> g_y_hi/lo (permuted) ------
__global__ void ln_kernel(const float* __restrict__ x) {
    const int tid = threadIdx.x;
    const int warp = tid >> 5, lane = tid & 31;
    const int row = blockIdx.x * 8 + warp;
    const int b = row >> 12;

    const float4 xv = *(const float4*)(x + row * 128 + lane * 4);
    float sum = xv.x + xv.y + xv.z + xv.w;
    float sq  = xv.x * xv.x + xv.y * xv.y + xv.z * xv.z + xv.w * xv.w;
#pragma unroll
    for (int o = 16; o; o >>= 1) {
        sum += __shfl_xor_sync(FULL, sum, o);
        sq  += __shfl_xor_sync(FULL, sq, o);
    }
    const float mean = sum * (1.0f / 128.0f);
    const float var  = sq * (1.0f / 128.0f) - mean * mean;
    const float rstd = rsqrtf(var + 1e-5f);

    const float4 sc = *(const float4*)(g_ada + b * 256 + lane * 4);
    const float4 sh = *(const float4*)(g_ada + b * 256 + 128 + lane * 4);
    float y0 = (xv.x - mean) * rstd * (1.0f + sc.x) + sh.x;
    float y1 = (xv.y - mean) * rstd * (1.0f + sc.y) + sh.y;
    float y2 = (xv.z - mean) * rstd * (1.0f + sc.z) + sh.z;
    float y3 = (xv.w - mean) * rstd * (1.0f + sc.w) + sh.w;

    uint32_t h0, l0, h1, l1, h2, l2, h3, l3;
    bsplit(y0, h0, l0); bsplit(y1, h1, l1);
    bsplit(y2, h2, l2); bsplit(y3, h3, l3);
    const int t0 = lane * 2;
    const int base = row * 64;
    g_y_hi[base + kperm(t0)]     = h0 | (h1 << 16);
    g_y_hi[base + kperm(t0 + 1)] = h2 | (h3 << 16);
    g_y_lo[base + kperm(t0)]     = l0 | (l1 << 16);
    g_y_lo[base + kperm(t0 + 1)] = l2 | (l3 << 16);
}

// ---------------- kernel C: qkv GEMM (3-term bf16, separate hi/lo) ------------
// grid(64, 6), block(256) = 8 warps (4m x 2n). tile 128x64, warp tile 32x32.
__global__ void __launch_bounds__(256)
qkv_gemm_tc(const float* __restrict__ bias) {
    extern __shared__ uint32_t smem[];
    uint32_t* sa_hi = smem;                      // [128][72]
    uint32_t* sa_lo = smem + 128 * 72;
    uint32_t* sb_hi = smem + 2 * 128 * 72;       // [64][72]
    uint32_t* sb_lo = smem + 2 * 128 * 72 + 64 * 72;

    const int tid = threadIdx.x;
    const int m0 = blockIdx.x * 128, n0 = blockIdx.y * 64;

#pragma unroll
    for (int r = 0; r < 8; r++) {
        const int id = tid + r * 256;
        const int row = id >> 4, j4 = id & 15;
        *(uint4*)(sa_hi + row * 72 + j4 * 4) =
            *(const uint4*)(g_y_hi + (m0 + row) * 64 + j4 * 4);
        *(uint4*)(sa_lo + row * 72 + j4 * 4) =
            *(const uint4*)(g_y_lo + (m0 + row) * 64 + j4 * 4);
    }
#pragma unroll
    for (int r = 0; r < 4; r++) {
        const int id = tid + r * 256;
        const int col = id >> 4, j4 = id & 15;
        *(uint4*)(sb_hi + col * 72 + j4 * 4) =
            *(const uint4*)(g_wqT_hi + (n0 + col) * 64 + j4 * 4);
        *(uint4*)(sb_lo + col * 72 + j4 * 4) =
            *(const uint4*)(g_wqT_lo + (n0 + col) * 64 + j4 * 4);
    }
    __syncthreads();

    const int lane = tid & 31, warp = tid >> 5;
    const int wm = warp & 3, wn = warp >> 2;
    const int g = lane >> 2, tig = lane & 3;

    float d[2][4][4];
#pragma unroll
    for (int fm = 0; fm < 2; fm++)
#pragma unroll
        for (int fn = 0; fn < 4; fn++)
#pragma unroll
            for (int e = 0; e < 4; e++) d[fm][fn][e] = 0.0f;

#pragma unroll
    for (int ks = 0; ks < 8; ks++) {
        const int base = ks * 8 + 2 * tig;
        uint32_t Ah[2][4], Al[2][4];
#pragma unroll
        for (int fm = 0; fm < 2; fm++) {
            const int r = wm * 32 + fm * 16 + g;
            const uint2 h0 = *(const uint2*)(sa_hi + r * 72 + base);
            const uint2 h1 = *(const uint2*)(sa_hi + (r + 8) * 72 + base);
            const uint2 l0 = *(const uint2*)(sa_lo + r * 72 + base);
            const uint2 l1 = *(const uint2*)(sa_lo + (r + 8) * 72 + base);
            Ah[fm][0] = h0.x; Ah[fm][1] = h1.x; Ah[fm][2] = h0.y; Ah[fm][3] = h1.y;
            Al[fm][0] = l0.x; Al[fm][1] = l1.x; Al[fm][2] = l0.y; Al[fm][3] = l1.y;
        }
#pragma unroll
        for (int fn = 0; fn < 4; fn++) {
            const int c = wn * 32 + fn * 8 + g;
            const uint2 bh = *(const uint2*)(sb_hi + c * 72 + base);
            const uint2 bl = *(const uint2*)(sb_lo + c * 72 + base);
            uint32_t Bh[2] = { bh.x, bh.y };
            uint32_t Bl[2] = { bl.x, bl.y };
#pragma unroll
            for (int fm = 0; fm < 2; fm++) {
                mma_bf16(d[fm][fn], Ah[fm], Bh);   // hi*hi
                mma_bf16(d[fm][fn], Al[fm], Bh);   // lo*hi
                mma_bf16(d[fm][fn], Ah[fm], Bl);   // hi*lo
            }
        }
    }

    const float qscale = 0.17677669529663687f;   // 32^-0.5
#pragma unroll
    for (int fn = 0; fn < 4; fn++) {
        const int j0 = n0 + wn * 32 + fn * 8 + 2 * tig;
        const float bv0 = bias[j0], bv1 = bias[j0 + 1];
        const int which = j0 >> 7;
        const int rem = j0 & 127;
        const int nh = rem >> 5, dd = rem & 31;
#pragma unroll
        for (int fm = 0; fm < 2; fm++) {
#pragma unroll
            for (int half = 0; half < 2; half++) {
                const int row = m0 + wm * 32 + fm * 16 + g + half * 8;
                const int bb = row >> 12, hh = (row >> 6) & 63, ww = row & 63;
                const int idx = (((bb * 4 + nh) * 64 + hh) * 64 + ww) * 32 + dd;
                float v0 = d[fm][fn][half * 2 + 0] + bv0;
                float v1 = d[fm][fn][half * 2 + 1] + bv1;
                if (which == 0) {
                    v0 *= qscale; v1 *= qscale;
                    *(float2*)(g_q + idx) = make_float2(v0, v1);
                } else if (which == 1) {
                    *(float2*)(g_k + idx) = make_float2(v0, v1);
                } else {
                    *(float2*)(g_v + idx) = make_float2(v0, v1);
                }
            }
        }
    }
}

// chunk set for d-half dh: {2dh, 2dh+1, 2dh+4, 2dh+5}. dh-flip = idx^2,
// row-half flip = sw^4 = idx^4 -> the 4 sibling lanes hit 4 distinct 16B groups.
__device__ __forceinline__ int cs_chunk(int dh, int jj) {
    return 2 * dh + (jj & 1) + ((jj & 2) << 1);
}

// ---------------- kernel D: natten, quarter-split, 1 h-row/block --------------
// grid(64 h, 8 bn), block(256) = 64 w x (2 row-half x 2 d-half).
// smem 57.4KB + launch_bounds(256,3) -> 85-reg budget, 3 blocks/SM, ~24 warps/SM.
// Two-phase K->V smem reuse; swizzle j ^ ((w+a)&7); compute (col+row)&7 form.
// Per-score d-half shfl executed by ALL lanes (na diverges lane-to-lane);
// only the store is guarded (inactive lanes read always-staged row 0).
__global__ void __launch_bounds__(256, 3)
natten_kernel(const float* __restrict__ rpb) {
    extern __shared__ float smem_f[];
    float* skv = smem_f;              // 7*64*32 = 14336 floats = 57344B
    float* srpb = smem_f + 14336;     // 169

    const int tid = threadIdx.x;
    const int h  = blockIdx.x;
    const int bn = blockIdx.y;
    const int b = bn >> 2, n = bn & 3;
    const int base = bn * (64 * 64 * 32);

    const int hs = nb_start(h);       // 7 rows staged: hs..hs+6

    // ---- phase 1: stage K ----
#pragma unroll 2
    for (int it = 0; it < 14; it++) {
        const int i = tid + it * 256;          // 14*256 = 3584 float4s
        const int a = i >> 9;
        const int rem = i & 511;
        const int w = rem >> 3, j = rem & 7;
        ((float4*)skv)[(a * 64 + w) * 8 + (j ^ ((w + a) & 7))] =
            *(const float4*)(g_k + base + (hs + a) * 2048 + w * 32 + j * 4);
    }
    for (int i = tid; i < 169; i += 256) srpb[i] = rpb[n * 169 + i];

    const int qw = tid >> 2;            // query column 0..63
    const int dh = tid & 1;             // d-half
    const int rh = (tid >> 1) & 1;      // row-half: 0 -> a 0..3, 1 -> a 4..6
    const int ws = nb_start(qw);
    const int rbase = (hs - h + 6) * 13 + (ws - qw + 6);
    const int a0 = rh * 4;
    const int na = 4 - rh;              // 4 or 3 rows

    float4 q4[4];
    {
        const int qoff = base + h * 2048 + qw * 32;
#pragma unroll
        for (int jj = 0; jj < 4; jj++)
            q4[jj] = *(const float4*)(g_q + qoff + 4 * cs_chunk(dh, jj));
    }
    __syncthreads();

    float s[28];
#pragma unroll
    for (int aa = 0; aa < 4; aa++) {
        const bool act = (aa < na);
        const int a = a0 + aa;
        const int row = act ? a : 0;           // dummy row 0 always staged
#pragma unroll
        for (int c = 0; c < 7; c++) {
            const int col = ws + c;
            const float4* kp = ((const float4*)skv) + (row * 64 + col) * 8;
            const int sw = (col + row) & 7;
            float p0 = 0.f, p1 = 0.f;
#pragma unroll
            for (int jj = 0; jj < 4; jj++) {
                const float4 kv = kp[cs_chunk(dh, jj) ^ sw];
                p0 += q4[jj].x * kv.x + q4[jj].y * kv.y;
                p1 += q4[jj].z * kv.z + q4[jj].w * kv.w;
            }
            float part = p0 + p1;
            part += __shfl_xor_sync(FULL, part, 1);  // ALL lanes: converged
            if (act) s[aa * 7 + c] = part + srpb[rbase + a * 13 + c];
        }
    }

    // softmax: combine row-halves (xor 2). d-halves already identical.
    float mloc = -INFINITY;
#pragma unroll
    for (int aa = 0; aa < 4; aa++)
        if (aa < na)
#pragma unroll
            for (int c = 0; c < 7; c++) mloc = fmaxf(mloc, s[aa * 7 + c]);
    const float m = fmaxf(mloc, __shfl_xor_sync(FULL, mloc, 2));

    float lloc = 0.f;
#pragma unroll
    for (int aa = 0; aa < 4; aa++)
        if (aa < na)
#pragma unroll
            for (int c = 0; c < 7; c++) {
                s[aa * 7 + c] = __expf(s[aa * 7 + c] - m);
                lloc += s[aa * 7 + c];
            }
    const float l = lloc + __shfl_xor_sync(FULL, lloc, 2);
    const float inv = 1.0f / l;

    __syncthreads();   // everyone done reading K

    // ---- phase 2: stage V into the same buffer ----
#pragma unroll 2
    for (int it = 0; it < 14; it++) {
        const int i = tid + it * 256;
        const int a = i >> 9;
        const int rem = i & 511;
        const int w_ = rem >> 3, j = rem & 7;
        ((float4*)skv)[(a * 64 + w_) * 8 + (j ^ ((w_ + a) & 7))] =
            *(const float4*)(g_v + base + (hs + a) * 2048 + w_ * 32 + j * 4);
    }
    __syncthreads();

    float4 acc[4];
#pragma unroll
    for (int jj = 0; jj < 4; jj++) acc[jj] = make_float4(0.f, 0.f, 0.f, 0.f);

#pragma unroll
    for (int aa = 0; aa < 4; aa++) {
        if (aa < na) {                                   // no collectives inside
            const int row = a0 + aa;
            const float4* vp = ((const float4*)skv) + (row * 64 + ws) * 8;
#pragma unroll
            for (int c = 0; c < 7; c++) {
                const int col = ws + c;
                const int sw = (col + row) & 7;
                const float p = s[aa * 7 + c];
#pragma unroll
                for (int jj = 0; jj < 4; jj++) {
                    const float4 vv = vp[c * 8 + (cs_chunk(dh, jj) ^ sw)];
                    acc[jj].x += p * vv.x;
                    acc[jj].y += p * vv.y;
                    acc[jj].z += p * vv.z;
                    acc[jj].w += p * vv.w;
                }
            }
        }
    }

    // combine row-halves (xor 2), asymmetric payload: rh0 ends with totals for
    // chunks cs(dh,0..1) = {2dh,2dh+1}; rh1 with cs(dh,2..3) = {2dh+4,2dh+5}.
    float4 send0 = rh ? acc[0] : acc[2];
    float4 send1 = rh ? acc[1] : acc[3];
    float4 recv0, recv1;
    recv0.x = __shfl_xor_sync(FULL, send0.x, 2);
    recv0.y = __shfl_xor_sync(FULL, send0.y, 2);
    recv0.z = __shfl_xor_sync(FULL, send0.z, 2);
    recv0.w = __shfl_xor_sync(FULL, send0.w, 2);
    recv1.x = __shfl_xor_sync(FULL, send1.x, 2);
    recv1.y = __shfl_xor_sync(FULL, send1.y, 2);
    recv1.z = __shfl_xor_sync(FULL, send1.z, 2);
    recv1.w = __shfl_xor_sync(FULL, send1.w, 2);
    const float4 mine0 = rh ? acc[2] : acc[0];
    const float4 mine1 = rh ? acc[3] : acc[1];

    float4 tot0, tot1;
    tot0.x = (mine0.x + recv0.x) * inv; tot0.y = (mine0.y + recv0.y) * inv;
    tot0.z = (mine0.z + recv0.z) * inv; tot0.w = (mine0.w + recv0.w) * inv;
    tot1.x = (mine1.x + recv1.x) * inv; tot1.y = (mine1.y + recv1.y) * inv;
    tot1.z = (mine1.z + recv1.z) * inv; tot1.w = (mine1.w + recv1.w) * inv;

    const int rowbase = ((b * 64 + h) * 64 + qw) * 64;
    const int chunk0 = 2 * dh + rh * 4;          // tot0 -> chunk0, tot1 -> chunk0+1
#pragma unroll
    for (int cc = 0; cc < 2; cc++) {
        const float4 tv = cc ? tot1 : tot0;
        const int chunk = chunk0 + cc;
        const int t = n * 16 + 2 * chunk;
        uint32_t hx, lx, hy, ly, hz, lz, hw, lw;
        bsplit(tv.x, hx, lx); bsplit(tv.y, hy, ly);
        bsplit(tv.z, hz, lz); bsplit(tv.w, hw, lw);
        g_att_hi[rowbase + kperm(t)]     = hx | (hy << 16);
        g_att_hi[rowbase + kperm(t + 1)] = hz | (hw << 16);
        g_att_lo[rowbase + kperm(t)]     = lx | (ly << 16);
        g_att_lo[rowbase + kperm(t + 1)] = lz | (lw << 16);
    }
}

// ---------------- kernel E: proj GEMM (3-term bf16, separate hi/lo) -----------
// grid(64, 2), block(256). tile 128x64.
__global__ void __launch_bounds__(256)
proj_gemm_tc(const float* __restrict__ bias, float* __restrict__ out) {
    extern __shared__ uint32_t smem[];
    uint32_t* sa_hi = smem;                      // [128][72]
    uint32_t* sa_lo = smem + 128 * 72;
    uint32_t* sb_hi = smem + 2 * 128 * 72;       // [64][72]
    uint32_t* sb_lo = smem + 2 * 128 * 72 + 64 * 72;

    const int tid = threadIdx.x;
    const int m0 = blockIdx.x * 128, n0 = blockIdx.y * 64;

#pragma unroll
    for (int r = 0; r < 8; r++) {
        const int id = tid + r * 256;
        const int row = id >> 4, j4 = id & 15;
        *(uint4*)(sa_hi + row * 72 + j4 * 4) =
            *(const uint4*)(g_att_hi + (m0 + row) * 64 + j4 * 4);
        *(uint4*)(sa_lo + row * 72 + j4 * 4) =
            *(const uint4*)(g_att_lo + (m0 + row) * 64 + j4 * 4);
    }
#pragma unroll
    for (int r = 0; r < 4; r++) {
        const int id = tid + r * 256;
        const int col = id >> 4, j4 = id & 15;
        *(uint4*)(sb_hi + col * 72 + j4 * 4) =
            *(const uint4*)(g_wpT_hi + (n0 + col) * 64 + j4 * 4);
        *(uint4*)(sb_lo + col * 72 + j4 * 4) =
            *(const uint4*)(g_wpT_lo + (n0 + col) * 64 + j4 * 4);
    }
    __syncthreads();

    const int lane = tid & 31, warp = tid >> 5;
    const int wm = warp & 3, wn = warp >> 2;
    const int g = lane >> 2, tig = lane & 3;

    float d[2][4][4];
#pragma unroll
    for (int fm = 0; fm < 2; fm++)
#pragma unroll
        for (int fn = 0; fn < 4; fn++)
#pragma unroll
            for (int e = 0; e < 4; e++) d[fm][fn][e] = 0.0f;

#pragma unroll
    for (int ks = 0; ks < 8; ks++) {
        const int base = ks * 8 + 2 * tig;
        uint32_t Ah[2][4], Al[2][4];
#pragma unroll
        for (int fm = 0; fm < 2; fm++) {
            const int r = wm * 32 + fm * 16 + g;
            const uint2 h0 = *(const uint2*)(sa_hi + r * 72 + base);
            const uint2 h1 = *(const uint2*)(sa_hi + (r + 8) * 72 + base);
            const uint2 l0 = *(const uint2*)(sa_lo + r * 72 + base);
            const uint2 l1 = *(const uint2*)(sa_lo + (r + 8) * 72 + base);
            Ah[fm][0] = h0.x; Ah[fm][1] = h1.x; Ah[fm][2] = h0.y; Ah[fm][3] = h1.y;
            Al[fm][0] = l0.x; Al[fm][1] = l1.x; Al[fm][2] = l0.y; Al[fm][3] = l1.y;
        }
#pragma unroll
        for (int fn = 0; fn < 4; fn++) {
            const int c = wn * 32 + fn * 8 + g;
            const uint2 bh = *(const uint2*)(sb_hi + c * 72 + base);
            const uint2 bl = *(const uint2*)(sb_lo + c * 72 + base);
            uint32_t Bh[2] = { bh.x, bh.y };
            uint32_t Bl[2] = { bl.x, bl.y };
#pragma unroll
            for (int fm = 0; fm < 2; fm++) {
                mma_bf16(d[fm][fn], Ah[fm], Bh);
                mma_bf16(d[fm][fn], Al[fm], Bh);
                mma_bf16(d[fm][fn], Ah[fm], Bl);
            }
        }
    }

#pragma unroll
    for (int fn = 0; fn < 4; fn++) {
        const int j0 = n0 + wn * 32 + fn * 8 + 2 * tig;
        const float bv0 = bias[j0], bv1 = bias[j0 + 1];
#pragma unroll
        for (int fm = 0; fm < 2; fm++) {
#pragma unroll
            for (int half = 0; half < 2; half++) {
                const int row = m0 + wm * 32 + fm * 16 + g + half * 8;
                float v0 = d[fm][fn][half * 2 + 0] + bv0;
                float v1 = d[fm][fn][half * 2 + 1] + bv1;
                *(float2*)(out + row * 128 + j0) = make_float2(v0, v1);
            }
        }
    }
}

// ---------------- launch ------------------------------------------------------
extern "C" void kernel_launch(void* const* d_in, const int* in_sizes, int n_in,
                              void* d_out, int out_size) {
    const float* x      = (const float*)d_in[0];
    // d_in[1] = cond (unused)
    const int*   t      = (const int*)d_in[2];
    const float* ln_w   = (const float*)d_in[3];
    const float* ln_b   = (const float*)d_in[4];
    const float* qkv_w  = (const float*)d_in[5];
    const float* qkv_b  = (const float*)d_in[6];
    const float* rpb    = (const float*)d_in[7];
    const float* proj_w = (const float*)d_in[8];
    const float* proj_b = (const float*)d_in[9];
    float* out = (float*)d_out;

    const int gemm_smem = (2 * 128 * 72 + 2 * 64 * 72) * 4;   // 110,592 B
    const int natten_smem = (14336 + 176) * 4;                // 58,048 B
    cudaFuncSetAttribute(qkv_gemm_tc,
                         cudaFuncAttributeMaxDynamicSharedMemorySize, gemm_smem);
    cudaFuncSetAttribute(proj_gemm_tc,
                         cudaFuncAttributeMaxDynamicSharedMemorySize, gemm_smem);
    cudaFuncSetAttribute(natten_kernel,
                         cudaFuncAttributeMaxDynamicSharedMemorySize, natten_smem);

    adaln_pack<<<10, 256>>>(t, ln_w, ln_b, qkv_w, proj_w);
    ln_kernel<<<1024, 256>>>(x);
    qkv_gemm_tc<<<dim3(64, 6), 256, gemm_smem>>>(qkv_b);
    natten_kernel<<<dim3(64, 8), 256, natten_smem>>>(rpb);
    proj_gemm_tc<<<dim3(64, 2), 256, gemm_smem>>>(proj_b, out);
}

// round 16
// speedup vs baseline: 1.1195x; 1.1195x over previous
#include <cuda_runtime.h>
#include <cuda_bf16.h>
#include <math.h>
#include <stdint.h>

#define FULL 0xFFFFFFFFu

// ---------------- scratch (device globals; no allocation allowed) -------------
__device__ float    g_ada[2 * 256];                 // [B, 2C] scale|shift
__device__ uint32_t g_y_hi[2 * 64 * 64 * 64];       // LN out hi, bf16x2, k-perm
__device__ uint32_t g_y_lo[2 * 64 * 64 * 64];       // LN out lo
__device__ uint32_t g_wqT_hi[384 * 64];             // qkv_w^T hi [n][kpair]
__device__ uint32_t g_wqT_lo[384 * 64];
__device__ uint32_t g_wpT_hi[128 * 64];             // proj_w^T hi
__device__ uint32_t g_wpT_lo[128 * 64];
__device__ float    g_q[2 * 4 * 64 * 64 * 32];      // [B,n,H,W,d]
__device__ float    g_k[2 * 4 * 64 * 64 * 32];
__device__ float    g_v[2 * 4 * 64 * 64 * 32];
__device__ float    g_attf[2 * 64 * 64 * 128];      // attention out fp32, float2 @ kperm pos

__device__ __forceinline__ int nb_start(int i) {
    int s = i - 3;
    s = s < 0 ? 0 : s;
    return s > 57 ? 57 : s;   // L-K = 64-7
}

// k-pair permutation: logical u32 index t -> physical position.
__device__ __forceinline__ int kperm(int t) {
    return (t & ~7) | ((t & 3) << 1) | ((t >> 2) & 1);
}

// split fp32 into bf16 hi and bf16 lo (as u16 bit patterns in u32)
__device__ __forceinline__ void bsplit(float x, uint32_t& h, uint32_t& l) {
    __nv_bfloat16 hb = __float2bfloat16(x);
    h = (uint32_t)__bfloat16_as_ushort(hb);
    l = (uint32_t)__bfloat16_as_ushort(__float2bfloat16(x - __bfloat162float(hb)));
}

__device__ __forceinline__ void mma_bf16(float* d, const uint32_t* a, const uint32_t* b) {
    asm("mma.sync.aligned.m16n8k16.row.col.f32.bf16.bf16.f32 "
        "{%0,%1,%2,%3}, {%4,%5,%6,%7}, {%8,%9}, {%0,%1,%2,%3};"
        : "+f"(d[0]), "+f"(d[1]), "+f"(d[2]), "+f"(d[3])
        : "r"(a[0]), "r"(a[1]), "r"(a[2]), "r"(a[3]), "r"(b[0]), "r"(b[1]));
}

// ---------------- kernel A: adaLN (blocks 0-1) + weight pack (blocks 2-9) -----
__global__ void adaln_pack(const int* __restrict__ t,
                           const float* __restrict__ ln_w,
                           const float* __restrict__ ln_b,
                           const float* __restrict__ qkv_w,
                           const float* __restrict__ proj_w) {
    __shared__ float tile[128][65];
    const int tid = threadIdx.x;

    if (blockIdx.x < 2) {
        float* s_silu = &tile[0][0];                 // reuse smem
        const int b = blockIdx.x;
        const float tf = (float)t[b] * 40.0f;        // t/100*4000
        if (tid < 64) {
            float f = __expf(-(float)tid * (9.210340371976184f / 63.0f));
            float e = tf * f;
            float se = sinf(e), ce = cosf(e);
            s_silu[tid]      = se / (1.0f + __expf(-se));
            s_silu[tid + 64] = ce / (1.0f + __expf(-ce));
        }
        __syncthreads();
        const int j = tid;
        float acc = ln_b[j];
#pragma unroll 16
        for (int k = 0; k < 128; k++) acc += s_silu[k] * ln_w[k * 256 + j];
        g_ada[b * 256 + j] = acc;
        return;
    }

    const int pb = blockIdx.x - 2;                   // 0..7
    const bool is_q = pb < 6;
    const float* W = is_q ? qkv_w : proj_w;
    const int stride = is_q ? 384 : 128;
    const int nbase = is_q ? pb * 64 : (pb - 6) * 64;
    uint32_t* dhi = is_q ? g_wqT_hi : g_wpT_hi;
    uint32_t* dlo = is_q ? g_wqT_lo : g_wpT_lo;

    for (int i = tid; i < 128 * 64; i += 256) {
        const int k = i >> 6, nn = i & 63;
        tile[k][nn] = W[k * stride + nbase + nn];
    }
    __syncthreads();

    for (int i = tid; i < 64 * 64; i += 256) {
        const int nn = i >> 6, tt = i & 63;
        uint32_t h0, l0, h1, l1;
        bsplit(tile[2 * tt][nn], h0, l0);
        bsplit(tile[2 * tt + 1][nn], h1, l1);
        const int pos = ((nbase + nn) << 6) | kperm(tt);
        dhi[pos] = h0 | (h1 << 16);
        dlo[pos] = l0 | (l1 << 16);
    }
}

// ---------------- kernel B: LayerNorm + modulate -> g_y_hi/lo (permuted) ------
__global__ void ln_kernel(const float* __restrict__ x) {
    const int tid = threadIdx.x;
    const int warp = tid >> 5, lane = tid & 31;
    const int row = blockIdx.x * 8 + warp;
    const int b = row >> 12;

    const float4 xv = *(const float4*)(x + row * 128 + lane * 4);
    float sum = xv.x + xv.y + xv.z + xv.w;
    float sq  = xv.x * xv.x + xv.y * xv.y + xv.z * xv.z + xv.w * xv.w;
#pragma unroll
    for (int o = 16; o; o >>= 1) {
        sum += __shfl_xor_sync(FULL, sum, o);
        sq  += __shfl_xor_sync(FULL, sq, o);
    }
    const float mean = sum * (1.0f / 128.0f);
    const float var  = sq * (1.0f / 128.0f) - mean * mean;
    const float rstd = rsqrtf(var + 1e-5f);

    const float4 sc = *(const float4*)(g_ada + b * 256 + lane * 4);
    const float4 sh = *(const float4*)(g_ada + b * 256 + 128 + lane * 4);
    float y0 = (xv.x - mean) * rstd * (1.0f + sc.x) + sh.x;
    float y1 = (xv.y - mean) * rstd * (1.0f + sc.y) + sh.y;
    float y2 = (xv.z - mean) * rstd * (1.0f + sc.z) + sh.z;
    float y3 = (xv.w - mean) * rstd * (1.0f + sc.w) + sh.w;

    uint32_t h0, l0, h1, l1, h2, l2, h3, l3;
    bsplit(y0, h0, l0); bsplit(y1, h1, l1);
    bsplit(y2, h2, l2); bsplit(y3, h3, l3);
    const int t0 = lane * 2;
    const int base = row * 64;
    g_y_hi[base + kperm(t0)]     = h0 | (h1 << 16);
    g_y_hi[base + kperm(t0 + 1)] = h2 | (h3 << 16);
    g_y_lo[base + kperm(t0)]     = l0 | (l1 << 16);
    g_y_lo[base + kperm(t0 + 1)] = l2 | (l3 << 16);
}

// ---------------- kernel C: qkv GEMM (3-term bf16, separate hi/lo) ------------
// grid(64, 6), block(256) = 8 warps (4m x 2n). tile 128x64, warp tile 32x32.
__global__ void __launch_bounds__(256)
qkv_gemm_tc(const float* __restrict__ bias) {
    extern __shared__ uint32_t smem[];
    uint32_t* sa_hi = smem;                      // [128][72]
    uint32_t* sa_lo = smem + 128 * 72;
    uint32_t* sb_hi = smem + 2 * 128 * 72;       // [64][72]
    uint32_t* sb_lo = smem + 2 * 128 * 72 + 64 * 72;

    const int tid = threadIdx.x;
    const int m0 = blockIdx.x * 128, n0 = blockIdx.y * 64;

#pragma unroll
    for (int r = 0; r < 8; r++) {
        const int id = tid + r * 256;
        const int row = id >> 4, j4 = id & 15;
        *(uint4*)(sa_hi + row * 72 + j4 * 4) =
            *(const uint4*)(g_y_hi + (m0 + row) * 64 + j4 * 4);
        *(uint4*)(sa_lo + row * 72 + j4 * 4) =
            *(const uint4*)(g_y_lo + (m0 + row) * 64 + j4 * 4);
    }
#pragma unroll
    for (int r = 0; r < 4; r++) {
        const int id = tid + r * 256;
        const int col = id >> 4, j4 = id & 15;
        *(uint4*)(sb_hi + col * 72 + j4 * 4) =
            *(const uint4*)(g_wqT_hi + (n0 + col) * 64 + j4 * 4);
        *(uint4*)(sb_lo + col * 72 + j4 * 4) =
            *(const uint4*)(g_wqT_lo + (n0 + col) * 64 + j4 * 4);
    }
    __syncthreads();

    const int lane = tid & 31, warp = tid >> 5;
    const int wm = warp & 3, wn = warp >> 2;
    const int g = lane >> 2, tig = lane & 3;

    float d[2][4][4];
#pragma unroll
    for (int fm = 0; fm < 2; fm++)
#pragma unroll
        for (int fn = 0; fn < 4; fn++)
#pragma unroll
            for (int e = 0; e < 4; e++) d[fm][fn][e] = 0.0f;

#pragma unroll
    for (int ks = 0; ks < 8; ks++) {
        const int base = ks * 8 + 2 * tig;
        uint32_t Ah[2][4], Al[2][4];
#pragma unroll
        for (int fm = 0; fm < 2; fm++) {
            const int r = wm * 32 + fm * 16 + g;
            const uint2 h0 = *(const uint2*)(sa_hi + r * 72 + base);
            const uint2 h1 = *(const uint2*)(sa_hi + (r + 8) * 72 + base);
            const uint2 l0 = *(const uint2*)(sa_lo + r * 72 + base);
            const uint2 l1 = *(const uint2*)(sa_lo + (r + 8) * 72 + base);
            Ah[fm][0] = h0.x; Ah[fm][1] = h1.x; Ah[fm][2] = h0.y; Ah[fm][3] = h1.y;
            Al[fm][0] = l0.x; Al[fm][1] = l1.x; Al[fm][2] = l0.y; Al[fm][3] = l1.y;
        }
#pragma unroll
        for (int fn = 0; fn < 4; fn++) {
            const int c = wn * 32 + fn * 8 + g;
            const uint2 bh = *(const uint2*)(sb_hi + c * 72 + base);
            const uint2 bl = *(const uint2*)(sb_lo + c * 72 + base);
            uint32_t Bh[2] = { bh.x, bh.y };
            uint32_t Bl[2] = { bl.x, bl.y };
#pragma unroll
            for (int fm = 0; fm < 2; fm++) {
                mma_bf16(d[fm][fn], Ah[fm], Bh);   // hi*hi
                mma_bf16(d[fm][fn], Al[fm], Bh);   // lo*hi
                mma_bf16(d[fm][fn], Ah[fm], Bl);   // hi*lo
            }
        }
    }

    const float qscale = 0.17677669529663687f;   // 32^-0.5
#pragma unroll
    for (int fn = 0; fn < 4; fn++) {
        const int j0 = n0 + wn * 32 + fn * 8 + 2 * tig;
        const float bv0 = bias[j0], bv1 = bias[j0 + 1];
        const int which = j0 >> 7;
        const int rem = j0 & 127;
        const int nh = rem >> 5, dd = rem & 31;
#pragma unroll
        for (int fm = 0; fm < 2; fm++) {
#pragma unroll
            for (int half = 0; half < 2; half++) {
                const int row = m0 + wm * 32 + fm * 16 + g + half * 8;
                const int bb = row >> 12, hh = (row >> 6) & 63, ww = row & 63;
                const int idx = (((bb * 4 + nh) * 64 + hh) * 64 + ww) * 32 + dd;
                float v0 = d[fm][fn][half * 2 + 0] + bv0;
                float v1 = d[fm][fn][half * 2 + 1] + bv1;
                if (which == 0) {
                    v0 *= qscale; v1 *= qscale;
                    *(float2*)(g_q + idx) = make_float2(v0, v1);
                } else if (which == 1) {
                    *(float2*)(g_k + idx) = make_float2(v0, v1);
                } else {
                    *(float2*)(g_v + idx) = make_float2(v0, v1);
                }
            }
        }
    }
}

// ---------------- kernel D: 7x7 neighborhood attention, row-split -------------
// grid(32 h-tiles, 8 bn), block(256) = 2 h-rows x 64 w x 2 row-halves.
// Pair of threads per query: half 0 -> key rows a=0..3, half 1 -> a=4..6.
// Two-phase K->V smem reuse; swizzle j ^ ((w+a)&7); compute (col+row)&7 form.
// Epilogue writes RAW fp32 float2s at kperm'd positions (no bsplit here —
// proj_gemm splits during staging). 8 coalescing-friendly STG.64 per thread.
__global__ void __launch_bounds__(256, 2)
natten_kernel(const float* __restrict__ rpb) {
    extern __shared__ float smem_f[];
    float* skv = smem_f;              // 8*64*32 = 16384 floats = 64KB
    float* srpb = smem_f + 16384;     // 169

    const int tid = threadIdx.x;
    const int h0 = blockIdx.x * 2;
    const int bn = blockIdx.y;
    const int b = bn >> 2, n = bn & 3;
    const int base = bn * (64 * 64 * 32);

    const int hs0 = nb_start(h0);
    const int nrows = nb_start(h0 + 1) + 6 - hs0 + 1;   // 7 or 8
    const int nchunks = nrows * 512;                     // rows*64*8 float4s

    // ---- phase 1: stage K ----
    for (int i = tid; i < nchunks; i += 256) {
        const int a = i >> 9;
        const int rem = i & 511;
        const int w = rem >> 3, j = rem & 7;
        ((float4*)skv)[(a * 64 + w) * 8 + (j ^ ((w + a) & 7))] =
            *(const float4*)(g_k + base + (hs0 + a) * 2048 + w * 32 + j * 4);
    }
    for (int i = tid; i < 169; i += 256) srpb[i] = rpb[n * 169 + i];
    __syncthreads();

    const int qidx = tid >> 1;         // 0..127
    const int half = tid & 1;          // row-half: 0 -> a 0..3, 1 -> a 4..6
    const int ih = qidx >> 6;
    const int w = qidx & 63;
    const int h = h0 + ih;
    const int ws = nb_start(w);
    const int hs_q = nb_start(h);
    const int arow0 = hs_q - hs0;
    const int rbase = (hs_q - h + 6) * 13 + (ws - w + 6);
    const int a0 = half * 4;
    const int na = 4 - half;           // 4 or 3 rows

    float4 q4[8];
    {
        const int qoff = base + h * 2048 + w * 32;
#pragma unroll
        for (int j = 0; j < 8; j++) q4[j] = *(const float4*)(g_q + qoff + 4 * j);
    }

    float s[28];
#pragma unroll
    for (int aa = 0; aa < 4; aa++) {
        if (aa < na) {
            const int a = a0 + aa;
            const int row = arow0 + a;
#pragma unroll
            for (int c = 0; c < 7; c++) {
                const int col = ws + c;
                const float4* kp = ((const float4*)skv) + (row * 64 + col) * 8;
                const int sw = (col + row) & 7;
                float p0 = 0.f, p1 = 0.f, p2 = 0.f, p3 = 0.f;
#pragma unroll
                for (int j = 0; j < 8; j++) {
                    const float4 kv = kp[j ^ sw];
                    p0 += q4[j].x * kv.x;
                    p1 += q4[j].y * kv.y;
                    p2 += q4[j].z * kv.z;
                    p3 += q4[j].w * kv.w;
                }
                s[aa * 7 + c] = (p0 + p1) + (p2 + p3) + srpb[rbase + a * 13 + c];
            }
        }
    }

    // pair softmax
    float mloc = -INFINITY;
#pragma unroll
    for (int aa = 0; aa < 4; aa++)
        if (aa < na)
#pragma unroll
            for (int c = 0; c < 7; c++) mloc = fmaxf(mloc, s[aa * 7 + c]);
    const float m = fmaxf(mloc, __shfl_xor_sync(FULL, mloc, 1));

    float lloc = 0.f;
#pragma unroll
    for (int aa = 0; aa < 4; aa++)
        if (aa < na)
#pragma unroll
            for (int c = 0; c < 7; c++) {
                s[aa * 7 + c] = __expf(s[aa * 7 + c] - m);
                lloc += s[aa * 7 + c];
            }
    const float l = lloc + __shfl_xor_sync(FULL, lloc, 1);
    const float inv = 1.0f / l;

    __syncthreads();   // everyone done reading K

    // ---- phase 2: stage V into the same buffer ----
    for (int i = tid; i < nchunks; i += 256) {
        const int a = i >> 9;
        const int rem = i & 511;
        const int w_ = rem >> 3, j = rem & 7;
        ((float4*)skv)[(a * 64 + w_) * 8 + (j ^ ((w_ + a) & 7))] =
            *(const float4*)(g_v + base + (hs0 + a) * 2048 + w_ * 32 + j * 4);
    }
    __syncthreads();

    float4 acc4[8];
#pragma unroll
    for (int j = 0; j < 8; j++) acc4[j] = make_float4(0.f, 0.f, 0.f, 0.f);

#pragma unroll
    for (int aa = 0; aa < 4; aa++) {
        if (aa < na) {
            const int a = a0 + aa;
            const int row = arow0 + a;
            const float4* vp = ((const float4*)skv) + (row * 64 + ws) * 8;
#pragma unroll
            for (int c = 0; c < 7; c++) {
                const int col = ws + c;
                const int sw = (col + row) & 7;          // addition mod 8
                const float p = s[aa * 7 + c];
#pragma unroll
                for (int j = 0; j < 8; j++) {
                    const float4 vv = vp[c * 8 + (j ^ sw)];
                    acc4[j].x += p * vv.x;
                    acc4[j].y += p * vv.y;
                    acc4[j].z += p * vv.z;
                    acc4[j].w += p * vv.w;
                }
            }
        }
    }

    // combine pair partial sums; write raw fp32 float2s at kperm'd positions.
    const int rowbase = ((b * 64 + h) * 64 + w) * 64;    // float2 units
    float2* outf2 = (float2*)g_attf;
#pragma unroll
    for (int j = 0; j < 4; j++) {
        const float4 send = half ? acc4[j] : acc4[j + 4];
        float4 recv;
        recv.x = __shfl_xor_sync(FULL, send.x, 1);
        recv.y = __shfl_xor_sync(FULL, send.y, 1);
        recv.z = __shfl_xor_sync(FULL, send.z, 1);
        recv.w = __shfl_xor_sync(FULL, send.w, 1);
        const float4 mine = half ? acc4[j + 4] : acc4[j];
        const float ox = (mine.x + recv.x) * inv;
        const float oy = (mine.y + recv.y) * inv;
        const float oz = (mine.z + recv.z) * inv;
        const float ow = (mine.w + recv.w) * inv;
        const int t = n * 16 + half * 8 + 2 * j;         // logical u32 index
        outf2[rowbase + kperm(t)]     = make_float2(ox, oy);
        outf2[rowbase + kperm(t + 1)] = make_float2(oz, ow);
    }
}

// ---------------- kernel E: proj GEMM (3-term bf16, separate hi/lo) -----------
// grid(64, 2), block(256). tile 128x64. A staged from raw fp32 (split here).
__global__ void __launch_bounds__(256)
proj_gemm_tc(const float* __restrict__ bias, float* __restrict__ out) {
    extern __shared__ uint32_t smem[];
    uint32_t* sa_hi = smem;                      // [128][72]
    uint32_t* sa_lo = smem + 128 * 72;
    uint32_t* sb_hi = smem + 2 * 128 * 72;       // [64][72]
    uint32_t* sb_lo = smem + 2 * 128 * 72 + 64 * 72;

    const int tid = threadIdx.x;
    const int m0 = blockIdx.x * 128, n0 = blockIdx.y * 64;

    // stage A: load fp32 float2 pairs (already kperm-ordered), split to hi/lo.
#pragma unroll
    for (int r = 0; r < 8; r++) {
        const int id = tid + r * 256;
        const int row = id >> 4, j4 = id & 15;
        const float2* src = (const float2*)g_attf + (m0 + row) * 64 + j4 * 4;
        uint4 hi, lo;
        {
            const float2 v0 = src[0], v1 = src[1], v2 = src[2], v3 = src[3];
            uint32_t ha, la, hb, lb;
            bsplit(v0.x, ha, la); bsplit(v0.y, hb, lb);
            hi.x = ha | (hb << 16); lo.x = la | (lb << 16);
            bsplit(v1.x, ha, la); bsplit(v1.y, hb, lb);
            hi.y = ha | (hb << 16); lo.y = la | (lb << 16);
            bsplit(v2.x, ha, la); bsplit(v2.y, hb, lb);
            hi.z = ha | (hb << 16); lo.z = la | (lb << 16);
            bsplit(v3.x, ha, la); bsplit(v3.y, hb, lb);
            hi.w = ha | (hb << 16); lo.w = la | (lb << 16);
        }
        *(uint4*)(sa_hi + row * 72 + j4 * 4) = hi;
        *(uint4*)(sa_lo + row * 72 + j4 * 4) = lo;
    }
#pragma unroll
    for (int r = 0; r < 4; r++) {
        const int id = tid + r * 256;
        const int col = id >> 4, j4 = id & 15;
        *(uint4*)(sb_hi + col * 72 + j4 * 4) =
            *(const uint4*)(g_wpT_hi + (n0 + col) * 64 + j4 * 4);
        *(uint4*)(sb_lo + col * 72 + j4 * 4) =
            *(const uint4*)(g_wpT_lo + (n0 + col) * 64 + j4 * 4);
    }
    __syncthreads();

    const int lane = tid & 31, warp = tid >> 5;
    const int wm = warp & 3, wn = warp >> 2;
    const int g = lane >> 2, tig = lane & 3;

    float d[2][4][4];
#pragma unroll
    for (int fm = 0; fm < 2; fm++)
#pragma unroll
        for (int fn = 0; fn < 4; fn++)
#pragma unroll
            for (int e = 0; e < 4; e++) d[fm][fn][e] = 0.0f;

#pragma unroll
    for (int ks = 0; ks < 8; ks++) {
        const int base = ks * 8 + 2 * tig;
        uint32_t Ah[2][4], Al[2][4];
#pragma unroll
        for (int fm = 0; fm < 2; fm++) {
            const int r = wm * 32 + fm * 16 + g;
            const uint2 h0 = *(const uint2*)(sa_hi + r * 72 + base);
            const uint2 h1 = *(const uint2*)(sa_hi + (r + 8) * 72 + base);
            const uint2 l0 = *(const uint2*)(sa_lo + r * 72 + base);
            const uint2 l1 = *(const uint2*)(sa_lo + (r + 8) * 72 + base);
            Ah[fm][0] = h0.x; Ah[fm][1] = h1.x; Ah[fm][2] = h0.y; Ah[fm][3] = h1.y;
            Al[fm][0] = l0.x; Al[fm][1] = l1.x; Al[fm][2] = l0.y; Al[fm][3] = l1.y;
        }
#pragma unroll
        for (int fn = 0; fn < 4; fn++) {
            const int c = wn * 32 + fn * 8 + g;
            const uint2 bh = *(const uint2*)(sb_hi + c * 72 + base);
            const uint2 bl = *(const uint2*)(sb_lo + c * 72 + base);
            uint32_t Bh[2] = { bh.x, bh.y };
            uint32_t Bl[2] = { bl.x, bl.y };
#pragma unroll
            for (int fm = 0; fm < 2; fm++) {
                mma_bf16(d[fm][fn], Ah[fm], Bh);
                mma_bf16(d[fm][fn], Al[fm], Bh);
                mma_bf16(d[fm][fn], Ah[fm], Bl);
            }
        }
    }

#pragma unroll
    for (int fn = 0; fn < 4; fn++) {
        const int j0 = n0 + wn * 32 + fn * 8 + 2 * tig;
        const float bv0 = bias[j0], bv1 = bias[j0 + 1];
#pragma unroll
        for (int fm = 0; fm < 2; fm++) {
#pragma unroll
            for (int half = 0; half < 2; half++) {
                const int row = m0 + wm * 32 + fm * 16 + g + half * 8;
                float v0 = d[fm][fn][half * 2 + 0] + bv0;
                float v1 = d[fm][fn][half * 2 + 1] + bv1;
                *(float2*)(out + row * 128 + j0) = make_float2(v0, v1);
            }
        }
    }
}

// ---------------- launch ------------------------------------------------------
extern "C" void kernel_launch(void* const* d_in, const int* in_sizes, int n_in,
                              void* d_out, int out_size) {
    const float* x      = (const float*)d_in[0];
    // d_in[1] = cond (unused)
    const int*   t      = (const int*)d_in[2];
    const float* ln_w   = (const float*)d_in[3];
    const float* ln_b   = (const float*)d_in[4];
    const float* qkv_w  = (const float*)d_in[5];
    const float* qkv_b  = (const float*)d_in[6];
    const float* rpb    = (const float*)d_in[7];
    const float* proj_w = (const float*)d_in[8];
    const float* proj_b = (const float*)d_in[9];
    float* out = (float*)d_out;

    const int gemm_smem = (2 * 128 * 72 + 2 * 64 * 72) * 4;   // 110,592 B
    const int natten_smem = (16384 + 176) * 4;                // 66,240 B
    cudaFuncSetAttribute(qkv_gemm_tc,
                         cudaFuncAttributeMaxDynamicSharedMemorySize, gemm_smem);
    cudaFuncSetAttribute(proj_gemm_tc,
                         cudaFuncAttributeMaxDynamicSharedMemorySize, gemm_smem);
    cudaFuncSetAttribute(natten_kernel,
                         cudaFuncAttributeMaxDynamicSharedMemorySize, natten_smem);

    adaln_pack<<<10, 256>>>(t, ln_w, ln_b, qkv_w, proj_w);
    ln_kernel<<<1024, 256>>>(x);
    qkv_gemm_tc<<<dim3(64, 6), 256, gemm_smem>>>(qkv_b);
    natten_kernel<<<dim3(32, 8), 256, natten_smem>>>(rpb);
    proj_gemm_tc<<<dim3(64, 2), 256, gemm_smem>>>(proj_b, out);
}